// round 5
// baseline (speedup 1.0000x reference)
#include <cuda_runtime.h>
#include <cuda_bf16.h>
#include <math.h>

#define NN 100000
#define EE 1600000
#define CC 64

#define SCAN_BS 512
#define SCAN_NB ((NN + SCAN_BS - 1) / SCAN_BS)   // 196

// ---------------- scratch (device globals; no allocation allowed) ----------------
__device__ float  g_deg[NN];
__device__ float  g_dinv[NN];
__device__ int    g_cnt[NN];      // in-degree count (for CSR)
__device__ int    g_ptr[NN];      // CSR row (segment) start
__device__ int    g_cur[NN];      // scatter cursors
__device__ int    g_bsum[SCAN_NB];
__device__ int    g_boff[SCAN_NB];
__device__ int    g_src[EE];      // CSR: source node per slot
__device__ float  g_nrm[EE];      // CSR: edge norm per slot
__device__ float4 g_h4[NN * 16];  // GEMM output (messages)
__device__ float4 g_gc4[NN * 16]; // aggregated + activated output

// ---------------- prep: degree + count ----------------
__global__ void k_init() {
    int i = blockIdx.x * blockDim.x + threadIdx.x;
    if (i < NN) { g_deg[i] = 1.0f; g_cnt[i] = 0; }   // self-loop weight 1
}

__global__ void k_count(const int* __restrict__ ei, const float* __restrict__ w) {
    int e = blockIdx.x * blockDim.x + threadIdx.x;
    if (e < EE) {
        int c = ei[EE + e];                // edge_index is int32 (JAX x64 disabled)
        atomicAdd(&g_deg[c], w[e]);
        atomicAdd(&g_cnt[c], 1);
    }
}

__global__ void k_dinv() {
    int i = blockIdx.x * blockDim.x + threadIdx.x;
    if (i < NN) {
        float d = g_deg[i];
        g_dinv[i] = (d > 0.0f) ? rsqrtf(d) : 0.0f;
    }
}

// ---------------- exclusive scan of g_cnt -> g_ptr ----------------
__global__ __launch_bounds__(SCAN_BS) void k_scan1() {
    __shared__ int sh[SCAN_BS];
    int t = threadIdx.x;
    int i = blockIdx.x * SCAN_BS + t;
    int v = (i < NN) ? g_cnt[i] : 0;
    sh[t] = v;
    __syncthreads();
#pragma unroll
    for (int off = 1; off < SCAN_BS; off <<= 1) {
        int x = (t >= off) ? sh[t - off] : 0;
        __syncthreads();
        sh[t] += x;
        __syncthreads();
    }
    if (i < NN) g_ptr[i] = sh[t] - v;              // exclusive within block
    if (t == SCAN_BS - 1) g_bsum[blockIdx.x] = sh[t];
}

__global__ __launch_bounds__(256) void k_scan2() {   // single block
    __shared__ int sh[256];
    int t = threadIdx.x;
    int v = (t < SCAN_NB) ? g_bsum[t] : 0;
    sh[t] = v;
    __syncthreads();
#pragma unroll
    for (int off = 1; off < 256; off <<= 1) {
        int x = (t >= off) ? sh[t - off] : 0;
        __syncthreads();
        sh[t] += x;
        __syncthreads();
    }
    if (t < SCAN_NB) g_boff[t] = sh[t] - v;        // exclusive
}

__global__ __launch_bounds__(SCAN_BS) void k_scan3() {
    int i = blockIdx.x * SCAN_BS + threadIdx.x;
    if (i < NN) {
        int p = g_ptr[i] + g_boff[blockIdx.x];
        g_ptr[i] = p;
        g_cur[i] = p;
    }
}

// ---------------- scatter edges into CSR slots (with norm) ----------------
__global__ void k_scatter(const int* __restrict__ ei, const float* __restrict__ w) {
    int e = blockIdx.x * blockDim.x + threadIdx.x;
    if (e < EE) {
        int r = ei[e];
        int c = ei[EE + e];
        float nrm = g_dinv[r] * w[e] * g_dinv[c];
        int slot = atomicAdd(&g_cur[c], 1);
        g_src[slot] = r;
        g_nrm[slot] = nrm;
    }
}

// ---------------- dense GEMM: g_h4[N,64] = x[N,64] @ W[64,64] ----------------
__device__ __forceinline__ void gemm64_body(const float* __restrict__ x,
                                            const float* __restrict__ W) {
    int c   = threadIdx.x & 63;
    int sub = threadIdx.x >> 6;   // 0..3
    float w[64];
#pragma unroll
    for (int k = 0; k < 64; k++) w[k] = __ldg(&W[k * 64 + c]);

    float* __restrict__ hout = (float*)g_h4;
    const int groups = NN / 4;
    for (int g = blockIdx.x; g < groups; g += gridDim.x) {
        int r = g * 4 + sub;
        const float4* xr = (const float4*)(x + (size_t)r * 64);
        float acc = 0.0f;
#pragma unroll
        for (int k4 = 0; k4 < 16; k4++) {
            float4 v = __ldg(xr + k4);
            acc = fmaf(v.x, w[4 * k4 + 0], acc);
            acc = fmaf(v.y, w[4 * k4 + 1], acc);
            acc = fmaf(v.z, w[4 * k4 + 2], acc);
            acc = fmaf(v.w, w[4 * k4 + 3], acc);
        }
        hout[(size_t)r * 64 + c] = acc;
    }
}

__global__ __launch_bounds__(256) void k_gemm_x(const float* __restrict__ x,
                                                const float* __restrict__ W) {
    gemm64_body(x, W);
}

__global__ __launch_bounds__(256) void k_gemm_gc(const float* __restrict__ W) {
    gemm64_body((const float*)g_gc4, W);
}

// ---------------- fused aggregation: gc = act( dinv^2*h + sum_e nrm*h[src] + b ) ----
// 16 lanes per node (one float4 per lane); 2 nodes per warp.
__global__ __launch_bounds__(256) void k_gather(const float* __restrict__ b, int relu) {
    int t = blockIdx.x * blockDim.x + threadIdx.x;
    int node = t >> 4;             // 16 threads per node
    if (node >= NN) return;
    int l16 = t & 15;

    float s = g_dinv[node];
    s = s * s;
    float4 acc = g_h4[(size_t)node * 16 + l16];
    acc.x *= s; acc.y *= s; acc.z *= s; acc.w *= s;

    int beg = g_ptr[node];
    int end = beg + g_cnt[node];
    for (int j = beg; j < end; j++) {
        int   src = __ldg(&g_src[j]);
        float nw  = __ldg(&g_nrm[j]);
        float4 v  = __ldg(&g_h4[(size_t)src * 16 + l16]);
        acc.x = fmaf(nw, v.x, acc.x);
        acc.y = fmaf(nw, v.y, acc.y);
        acc.z = fmaf(nw, v.z, acc.z);
        acc.w = fmaf(nw, v.w, acc.w);
    }

    float4 bb = __ldg(((const float4*)b) + l16);
    acc.x += bb.x; acc.y += bb.y; acc.z += bb.z; acc.w += bb.w;
    if (relu) {
        acc.x = fmaxf(acc.x, 0.0f); acc.y = fmaxf(acc.y, 0.0f);
        acc.z = fmaxf(acc.z, 0.0f); acc.w = fmaxf(acc.w, 0.0f);
    } else {
        acc.x = 1.0f / (1.0f + expf(-acc.x));
        acc.y = 1.0f / (1.0f + expf(-acc.y));
        acc.z = 1.0f / (1.0f + expf(-acc.z));
        acc.w = 1.0f / (1.0f + expf(-acc.w));
    }
    g_gc4[(size_t)node * 16 + l16] = acc;
}

// ---------------- fused GRU gates ----------------
// 192 threads: t/64 = gate (0=z,1=r,2=h), t%64 = output channel.
__global__ __launch_bounds__(192) void k_gates(const float* __restrict__ Hm,
                                               const float* __restrict__ Wz, const float* __restrict__ bz,
                                               const float* __restrict__ Wr, const float* __restrict__ br,
                                               const float* __restrict__ Wh, const float* __restrict__ bh,
                                               float* __restrict__ out) {
    int t = threadIdx.x;
    int gate = t >> 6;
    int c = t & 63;
    const float* W = (gate == 0) ? Wz : (gate == 1) ? Wr : Wh;
    float bias = ((gate == 0) ? bz : (gate == 1) ? br : bh)[c];
    float w[128];
#pragma unroll
    for (int k = 0; k < 128; k++) w[k] = __ldg(&W[k * 64 + c]);

    __shared__ float s_x[128];    // [0:64) GC row, [64:128) H row
    __shared__ float s_zr[128];   // [0:64) Z, [64:128) R
    __shared__ float s_ht[64];

    const float* gc = (const float*)g_gc4;

    for (int r = blockIdx.x; r < NN; r += gridDim.x) {
        __syncthreads();
        if (t < 128) {
            const float* src = (t < 64) ? (gc + (size_t)r * 64 + t)
                                        : (Hm + (size_t)r * 64 + (t - 64));
            s_x[t] = __ldg(src);
        }
        __syncthreads();

        float acc = bias;
        const float4* x4 = (const float4*)s_x;
        if (gate < 2) {
#pragma unroll
            for (int k4 = 0; k4 < 32; k4++) {
                float4 v = x4[k4];
                acc = fmaf(v.x, w[4 * k4 + 0], acc);
                acc = fmaf(v.y, w[4 * k4 + 1], acc);
                acc = fmaf(v.z, w[4 * k4 + 2], acc);
                acc = fmaf(v.w, w[4 * k4 + 3], acc);
            }
            s_zr[gate * 64 + c] = 1.0f / (1.0f + expf(-acc));
        } else {
#pragma unroll
            for (int k4 = 0; k4 < 16; k4++) {      // GC half
                float4 v = x4[k4];
                acc = fmaf(v.x, w[4 * k4 + 0], acc);
                acc = fmaf(v.y, w[4 * k4 + 1], acc);
                acc = fmaf(v.z, w[4 * k4 + 2], acc);
                acc = fmaf(v.w, w[4 * k4 + 3], acc);
            }
        }
        __syncthreads();

        if (gate == 2) {
            const float4* zr4 = (const float4*)s_zr;
#pragma unroll
            for (int k4 = 0; k4 < 16; k4++) {      // (H*R) half
                float4 hv = x4[16 + k4];
                float4 rv = zr4[16 + k4];
                acc = fmaf(hv.x * rv.x, w[64 + 4 * k4 + 0], acc);
                acc = fmaf(hv.y * rv.y, w[64 + 4 * k4 + 1], acc);
                acc = fmaf(hv.z * rv.z, w[64 + 4 * k4 + 2], acc);
                acc = fmaf(hv.w * rv.w, w[64 + 4 * k4 + 3], acc);
            }
            s_ht[c] = tanhf(acc);
        }
        __syncthreads();

        if (gate == 0) {
            float z = s_zr[c];
            float hv = s_x[64 + c];
            out[(size_t)r * 64 + c] = z * hv + (1.0f - z) * s_ht[c];
        }
    }
}

// ---------------- launch ----------------
extern "C" void kernel_launch(void* const* d_in, const int* in_sizes, int n_in,
                              void* d_out, int out_size) {
    const float* X  = (const float*)d_in[0];
    const int*   EI = (const int*)d_in[1];     // int32! (JAX default x64 disabled)
    const float* EW = (const float*)d_in[2];
    const float* H  = (const float*)d_in[3];
    const float* W1 = (const float*)d_in[4];
    const float* b1 = (const float*)d_in[5];
    const float* W2 = (const float*)d_in[6];
    const float* b2 = (const float*)d_in[7];
    const float* Wz = (const float*)d_in[8];
    const float* bz = (const float*)d_in[9];
    const float* Wr = (const float*)d_in[10];
    const float* br = (const float*)d_in[11];
    const float* Wh = (const float*)d_in[12];
    const float* bh = (const float*)d_in[13];
    float* out = (float*)d_out;

    const int TB = 256;
    const int nBlkN   = (NN + TB - 1) / TB;
    const int nBlkE   = (EE + TB - 1) / TB;
    const int nBlkGat = (NN * 16 + TB - 1) / TB;

    // ---- prep: degree, CSR build ----
    k_init<<<nBlkN, TB>>>();
    k_count<<<nBlkE, TB>>>(EI, EW);
    k_dinv<<<nBlkN, TB>>>();
    k_scan1<<<SCAN_NB, SCAN_BS>>>();
    k_scan2<<<1, 256>>>();
    k_scan3<<<SCAN_NB, SCAN_BS>>>();
    k_scatter<<<nBlkE, TB>>>(EI, EW);

    // ---- layer 1 ----
    k_gemm_x<<<1024, TB>>>(X, W1);
    k_gather<<<nBlkGat, TB>>>(b1, 1);   // relu -> g_gc4

    // ---- layer 2 ----
    k_gemm_gc<<<1024, TB>>>(W2);
    k_gather<<<nBlkGat, TB>>>(b2, 0);   // sigmoid -> g_gc4

    // ---- GRU gates ----
    k_gates<<<1184, 192>>>(H, Wz, bz, Wr, br, Wh, bh, out);
}

// round 7
// speedup vs baseline: 1.3973x; 1.3973x over previous
#include <cuda_runtime.h>
#include <cuda_bf16.h>
#include <math.h>

#define NN 100000
#define EE 1600000
#define CC 64

#define SCAN_BS 512
#define SCAN_NB ((NN + SCAN_BS - 1) / SCAN_BS)   // 196

// ---------------- scratch (device globals; no allocation allowed) ----------------
__device__ float  g_deg[NN];
__device__ float  g_dinv[NN];
__device__ int    g_cnt[NN];      // in-degree count (for CSR)
__device__ int    g_ptr[NN];      // CSR segment start
__device__ int    g_cur[NN];      // scatter cursors (== segment end after scatter)
__device__ int    g_bsum[SCAN_NB];
__device__ int    g_boff[SCAN_NB];
__device__ int2   g_edge[EE];     // CSR slot: {src, float_bits(norm)}
__device__ float4 g_h4[NN * 16];  // GEMM output (messages)
__device__ float4 g_gc4[NN * 16]; // aggregated + activated output

// ---------------- fast activations (2-ulp class, saturation-safe) ----------------
__device__ __forceinline__ float f_sig(float x) {
    // x<<0: expf(-x)=inf -> 0 ; x>>0: expf(-x)=0 -> 1
    return __fdividef(1.0f, 1.0f + __expf(-x));
}
__device__ __forceinline__ float f_tanh(float x) {
    // 1 - 2/(e^{2x}+1): e=inf -> 1 ; e=0 -> -1 (no inf/inf NaN)
    return 1.0f - __fdividef(2.0f, __expf(2.0f * x) + 1.0f);
}

// ---------------- prep: degree + count ----------------
__global__ void k_init() {
    int i = blockIdx.x * blockDim.x + threadIdx.x;
    if (i < NN) { g_deg[i] = 1.0f; g_cnt[i] = 0; }   // self-loop weight 1
}

__global__ void k_count(const int* __restrict__ ei, const float* __restrict__ w) {
    int e = blockIdx.x * blockDim.x + threadIdx.x;
    if (e < EE) {
        int c = ei[EE + e];                // int32 edge_index
        atomicAdd(&g_deg[c], w[e]);
        atomicAdd(&g_cnt[c], 1);
    }
}

// ---------------- scan1 (+ fused dinv) ----------------
__global__ __launch_bounds__(SCAN_BS) void k_scan1() {
    __shared__ int sh[SCAN_BS];
    int t = threadIdx.x;
    int i = blockIdx.x * SCAN_BS + t;
    if (i < NN) {                          // fused: dinv from final degree
        float d = g_deg[i];
        g_dinv[i] = (d > 0.0f) ? rsqrtf(d) : 0.0f;
    }
    int v = (i < NN) ? g_cnt[i] : 0;
    sh[t] = v;
    __syncthreads();
#pragma unroll
    for (int off = 1; off < SCAN_BS; off <<= 1) {
        int x = (t >= off) ? sh[t - off] : 0;
        __syncthreads();
        sh[t] += x;
        __syncthreads();
    }
    if (i < NN) g_ptr[i] = sh[t] - v;              // exclusive within block
    if (t == SCAN_BS - 1) g_bsum[blockIdx.x] = sh[t];
}

__global__ __launch_bounds__(256) void k_scan2() {   // single block
    __shared__ int sh[256];
    int t = threadIdx.x;
    int v = (t < SCAN_NB) ? g_bsum[t] : 0;
    sh[t] = v;
    __syncthreads();
#pragma unroll
    for (int off = 1; off < 256; off <<= 1) {
        int x = (t >= off) ? sh[t - off] : 0;
        __syncthreads();
        sh[t] += x;
        __syncthreads();
    }
    if (t < SCAN_NB) g_boff[t] = sh[t] - v;        // exclusive
}

__global__ __launch_bounds__(SCAN_BS) void k_scan3() {
    int i = blockIdx.x * SCAN_BS + threadIdx.x;
    if (i < NN) {
        int p = g_ptr[i] + g_boff[blockIdx.x];
        g_ptr[i] = p;
        g_cur[i] = p;
    }
}

// ---------------- scatter edges into CSR slots (with norm) ----------------
__global__ void k_scatter(const int* __restrict__ ei, const float* __restrict__ w) {
    int e = blockIdx.x * blockDim.x + threadIdx.x;
    if (e < EE) {
        int r = ei[e];
        int c = ei[EE + e];
        float nrm = g_dinv[r] * w[e] * g_dinv[c];
        int slot = atomicAdd(&g_cur[c], 1);
        g_edge[slot] = make_int2(r, __float_as_int(nrm));
    }
}

// ---------------- dense GEMM: g_h4[N,64] = x[N,64] @ W[64,64] ----------------
__device__ __forceinline__ void gemm64_body(const float* __restrict__ x,
                                            const float* __restrict__ W) {
    int c   = threadIdx.x & 63;
    int sub = threadIdx.x >> 6;   // 0..3
    float w[64];
#pragma unroll
    for (int k = 0; k < 64; k++) w[k] = __ldg(&W[k * 64 + c]);

    float* __restrict__ hout = (float*)g_h4;
    const int groups = NN / 4;
    for (int g = blockIdx.x; g < groups; g += gridDim.x) {
        int r = g * 4 + sub;
        const float4* xr = (const float4*)(x + (size_t)r * 64);
        float acc = 0.0f;
#pragma unroll
        for (int k4 = 0; k4 < 16; k4++) {
            float4 v = __ldg(xr + k4);
            acc = fmaf(v.x, w[4 * k4 + 0], acc);
            acc = fmaf(v.y, w[4 * k4 + 1], acc);
            acc = fmaf(v.z, w[4 * k4 + 2], acc);
            acc = fmaf(v.w, w[4 * k4 + 3], acc);
        }
        hout[(size_t)r * 64 + c] = acc;
    }
}

__global__ __launch_bounds__(256) void k_gemm_x(const float* __restrict__ x,
                                                const float* __restrict__ W) {
    gemm64_body(x, W);
}

__global__ __launch_bounds__(256) void k_gemm_gc(const float* __restrict__ W) {
    gemm64_body((const float*)g_gc4, W);
}

// ---------------- fused aggregation: gc = act( dinv^2*h + sum_e nrm*h[src] + b ) ----
// 16 lanes per node (one float4 per lane); 2 nodes per warp.
__global__ __launch_bounds__(256) void k_gather(const float* __restrict__ b, int relu) {
    int t = blockIdx.x * blockDim.x + threadIdx.x;
    int node = t >> 4;
    if (node >= NN) return;
    int l16 = t & 15;

    float s = g_dinv[node];
    s = s * s;
    float4 acc = g_h4[(size_t)node * 16 + l16];
    acc.x *= s; acc.y *= s; acc.z *= s; acc.w *= s;

    int j   = g_ptr[node];
    int end = g_cur[node];           // == ptr + cnt after scatter
    // 2-deep manual unroll to raise MLP across the (index -> feature) chain
    for (; j + 1 < end; j += 2) {
        int2 e0 = __ldg(&g_edge[j]);
        int2 e1 = __ldg(&g_edge[j + 1]);
        float4 v0 = __ldg(&g_h4[(size_t)e0.x * 16 + l16]);
        float4 v1 = __ldg(&g_h4[(size_t)e1.x * 16 + l16]);
        float n0 = __int_as_float(e0.y);
        float n1 = __int_as_float(e1.y);
        acc.x = fmaf(n0, v0.x, acc.x); acc.y = fmaf(n0, v0.y, acc.y);
        acc.z = fmaf(n0, v0.z, acc.z); acc.w = fmaf(n0, v0.w, acc.w);
        acc.x = fmaf(n1, v1.x, acc.x); acc.y = fmaf(n1, v1.y, acc.y);
        acc.z = fmaf(n1, v1.z, acc.z); acc.w = fmaf(n1, v1.w, acc.w);
    }
    if (j < end) {
        int2 e0 = __ldg(&g_edge[j]);
        float4 v0 = __ldg(&g_h4[(size_t)e0.x * 16 + l16]);
        float n0 = __int_as_float(e0.y);
        acc.x = fmaf(n0, v0.x, acc.x); acc.y = fmaf(n0, v0.y, acc.y);
        acc.z = fmaf(n0, v0.z, acc.z); acc.w = fmaf(n0, v0.w, acc.w);
    }

    float4 bb = __ldg(((const float4*)b) + l16);
    acc.x += bb.x; acc.y += bb.y; acc.z += bb.z; acc.w += bb.w;
    if (relu) {
        acc.x = fmaxf(acc.x, 0.0f); acc.y = fmaxf(acc.y, 0.0f);
        acc.z = fmaxf(acc.z, 0.0f); acc.w = fmaxf(acc.w, 0.0f);
    } else {
        acc.x = f_sig(acc.x); acc.y = f_sig(acc.y);
        acc.z = f_sig(acc.z); acc.w = f_sig(acc.w);
    }
    g_gc4[(size_t)node * 16 + l16] = acc;
}

// ---------------- fused GRU gates, 4 rows per sync epoch ----------------
// 192 threads: t/64 = gate (0=z,1=r,2=h), t%64 = output channel.
// Each thread owns its 128-deep weight column in registers; 4 independent
// row-accumulators give ILP to cover the FFMA RAW latency.
__global__ __launch_bounds__(192) void k_gates(const float* __restrict__ Hm,
                                               const float* __restrict__ Wz, const float* __restrict__ bz,
                                               const float* __restrict__ Wr, const float* __restrict__ br,
                                               const float* __restrict__ Wh, const float* __restrict__ bh,
                                               float* __restrict__ out) {
    int t = threadIdx.x;
    int gate = t >> 6;
    int c = t & 63;
    const float* W = (gate == 0) ? Wz : (gate == 1) ? Wr : Wh;
    float bias = ((gate == 0) ? bz : (gate == 1) ? br : bh)[c];
    float w[128];
#pragma unroll
    for (int k = 0; k < 128; k++) w[k] = __ldg(&W[k * 64 + c]);

    __shared__ float s_x[4][128];    // per row: [0:64) GC, [64:128) H
    __shared__ float s_zr[4][128];   // per row: [0:64) Z, [64:128) R
    __shared__ float s_ht[4][64];

    const float* gc = (const float*)g_gc4;
    const int groups = NN / 4;       // 25000

    for (int g = blockIdx.x; g < groups; g += gridDim.x) {
        int r0 = g * 4;
        __syncthreads();
        if (t < 128) {
            const float* base = (t < 64) ? (gc + (size_t)r0 * 64 + t)
                                         : (Hm + (size_t)r0 * 64 + (t - 64));
#pragma unroll
            for (int rr = 0; rr < 4; rr++) s_x[rr][t] = __ldg(base + rr * 64);
        }
        __syncthreads();

        float acc[4];
#pragma unroll
        for (int rr = 0; rr < 4; rr++) acc[rr] = bias;

        if (gate < 2) {
#pragma unroll
            for (int k4 = 0; k4 < 32; k4++) {
#pragma unroll
                for (int rr = 0; rr < 4; rr++) {
                    float4 v = ((const float4*)s_x[rr])[k4];
                    acc[rr] = fmaf(v.x, w[4 * k4 + 0], acc[rr]);
                    acc[rr] = fmaf(v.y, w[4 * k4 + 1], acc[rr]);
                    acc[rr] = fmaf(v.z, w[4 * k4 + 2], acc[rr]);
                    acc[rr] = fmaf(v.w, w[4 * k4 + 3], acc[rr]);
                }
            }
#pragma unroll
            for (int rr = 0; rr < 4; rr++)
                s_zr[rr][gate * 64 + c] = f_sig(acc[rr]);
        } else {
#pragma unroll
            for (int k4 = 0; k4 < 16; k4++) {      // GC half
#pragma unroll
                for (int rr = 0; rr < 4; rr++) {
                    float4 v = ((const float4*)s_x[rr])[k4];
                    acc[rr] = fmaf(v.x, w[4 * k4 + 0], acc[rr]);
                    acc[rr] = fmaf(v.y, w[4 * k4 + 1], acc[rr]);
                    acc[rr] = fmaf(v.z, w[4 * k4 + 2], acc[rr]);
                    acc[rr] = fmaf(v.w, w[4 * k4 + 3], acc[rr]);
                }
            }
        }
        __syncthreads();

        if (gate == 2) {
#pragma unroll
            for (int k4 = 0; k4 < 16; k4++) {      // (H*R) half
#pragma unroll
                for (int rr = 0; rr < 4; rr++) {
                    float4 hv = ((const float4*)s_x[rr])[16 + k4];
                    float4 rv = ((const float4*)s_zr[rr])[16 + k4];
                    acc[rr] = fmaf(hv.x * rv.x, w[64 + 4 * k4 + 0], acc[rr]);
                    acc[rr] = fmaf(hv.y * rv.y, w[64 + 4 * k4 + 1], acc[rr]);
                    acc[rr] = fmaf(hv.z * rv.z, w[64 + 4 * k4 + 2], acc[rr]);
                    acc[rr] = fmaf(hv.w * rv.w, w[64 + 4 * k4 + 3], acc[rr]);
                }
            }
#pragma unroll
            for (int rr = 0; rr < 4; rr++) s_ht[rr][c] = f_tanh(acc[rr]);
        }
        __syncthreads();

        if (gate == 0) {
#pragma unroll
            for (int rr = 0; rr < 4; rr++) {
                float z  = s_zr[rr][c];
                float hv = s_x[rr][64 + c];
                out[(size_t)(r0 + rr) * 64 + c] = z * hv + (1.0f - z) * s_ht[rr][c];
            }
        }
    }
}

// ---------------- launch ----------------
extern "C" void kernel_launch(void* const* d_in, const int* in_sizes, int n_in,
                              void* d_out, int out_size) {
    const float* X  = (const float*)d_in[0];
    const int*   EI = (const int*)d_in[1];     // int32 (JAX default x64 disabled)
    const float* EW = (const float*)d_in[2];
    const float* H  = (const float*)d_in[3];
    const float* W1 = (const float*)d_in[4];
    const float* b1 = (const float*)d_in[5];
    const float* W2 = (const float*)d_in[6];
    const float* b2 = (const float*)d_in[7];
    const float* Wz = (const float*)d_in[8];
    const float* bz = (const float*)d_in[9];
    const float* Wr = (const float*)d_in[10];
    const float* br = (const float*)d_in[11];
    const float* Wh = (const float*)d_in[12];
    const float* bh = (const float*)d_in[13];
    float* out = (float*)d_out;

    const int TB = 256;
    const int nBlkN   = (NN + TB - 1) / TB;
    const int nBlkE   = (EE + TB - 1) / TB;
    const int nBlkGat = (NN * 16 + TB - 1) / TB;

    // ---- prep: degree, CSR build ----
    k_init<<<nBlkN, TB>>>();
    k_count<<<nBlkE, TB>>>(EI, EW);
    k_scan1<<<SCAN_NB, SCAN_BS>>>();       // includes dinv
    k_scan2<<<1, 256>>>();
    k_scan3<<<SCAN_NB, SCAN_BS>>>();
    k_scatter<<<nBlkE, TB>>>(EI, EW);

    // ---- layer 1 ----
    k_gemm_x<<<1024, TB>>>(X, W1);
    k_gather<<<nBlkGat, TB>>>(b1, 1);   // relu -> g_gc4

    // ---- layer 2 ----
    k_gemm_gc<<<1024, TB>>>(W2);
    k_gather<<<nBlkGat, TB>>>(b2, 0);   // sigmoid -> g_gc4

    // ---- GRU gates ----
    k_gates<<<592, 192>>>(H, Wz, bz, Wr, br, Wh, bh, out);
}